// round 8
// baseline (speedup 1.0000x reference)
#include <cuda_runtime.h>
#include <cuda_bf16.h>
#include <math.h>
#include <float.h>
#include <stdint.h>

// Problem constants (match reference)
#define NN 100000
#define NE 1600000
#define NF 128
#define NL 7
#define SLOPE 0.02f

// ---------------- device scratch (static, no allocation) ----------------
// zero-initialized at load; g_counts re-zeroed by fill_kernel, g_cursor by
// scan_kernel each call -> deterministic across calls.
__device__ int   g_counts[NN];
__device__ int   g_cursor[NN];
__device__ int   g_rowptr[NN + 1];
__device__ int   g_col[NE];
// activations live ONLY as pre-split bf16 hi/lo planes (hi+lo ~= 17-bit value)
__device__ __align__(16) uint16_t g_h0Hi[NN * NF];
__device__ __align__(16) uint16_t g_h0Lo[NN * NF];
__device__ __align__(16) uint16_t g_h1Hi[NN * NF];
__device__ __align__(16) uint16_t g_h1Lo[NN * NF];
__device__ __align__(16) uint16_t g_aggHi[NN * NF];
__device__ __align__(16) uint16_t g_aggLo[NN * NF];
// pre-split weights: hi/lo bf16, layout [l][n][k] (same as input W)
__device__ __align__(16) uint16_t g_WlHi[NL * NF * NF];
__device__ __align__(16) uint16_t g_WlLo[NL * NF * NF];
__device__ __align__(16) uint16_t g_WrHi[NL * NF * NF];
__device__ __align__(16) uint16_t g_WrLo[NL * NF * NF];

// ---------------- split/reconstruct helpers ----------------
__device__ __forceinline__ void split4_store(uint16_t* __restrict__ Hi,
                                             uint16_t* __restrict__ Lo,
                                             int idx4, float4 v) {
    __nv_bfloat16 hx = __float2bfloat16(v.x);
    __nv_bfloat16 hy = __float2bfloat16(v.y);
    __nv_bfloat16 hz = __float2bfloat16(v.z);
    __nv_bfloat16 hw = __float2bfloat16(v.w);
    uint32_t hi01 = ((uint32_t)__bfloat16_as_ushort(hy) << 16) | __bfloat16_as_ushort(hx);
    uint32_t hi23 = ((uint32_t)__bfloat16_as_ushort(hw) << 16) | __bfloat16_as_ushort(hz);
    __nv_bfloat16 lx = __float2bfloat16(v.x - __bfloat162float(hx));
    __nv_bfloat16 ly = __float2bfloat16(v.y - __bfloat162float(hy));
    __nv_bfloat16 lz = __float2bfloat16(v.z - __bfloat162float(hz));
    __nv_bfloat16 lw = __float2bfloat16(v.w - __bfloat162float(hw));
    uint32_t lo01 = ((uint32_t)__bfloat16_as_ushort(ly) << 16) | __bfloat16_as_ushort(lx);
    uint32_t lo23 = ((uint32_t)__bfloat16_as_ushort(lw) << 16) | __bfloat16_as_ushort(lz);
    ((uint2*)Hi)[idx4] = make_uint2(hi01, hi23);
    ((uint2*)Lo)[idx4] = make_uint2(lo01, lo23);
}

__device__ __forceinline__ float4 rec4(uint2 h, uint2 l) {
    float4 v;
    v.x = __uint_as_float(h.x << 16)         + __uint_as_float(l.x << 16);
    v.y = __uint_as_float(h.x & 0xffff0000u) + __uint_as_float(l.x & 0xffff0000u);
    v.z = __uint_as_float(h.y << 16)         + __uint_as_float(l.y << 16);
    v.w = __uint_as_float(h.y & 0xffff0000u) + __uint_as_float(l.y & 0xffff0000u);
    return v;
}

__device__ __forceinline__ void split2_store(uint16_t* __restrict__ Hi,
                                             uint16_t* __restrict__ Lo,
                                             size_t elt, float a, float b) {
    __nv_bfloat16 ha = __float2bfloat16(a), hb = __float2bfloat16(b);
    uint32_t hi = ((uint32_t)__bfloat16_as_ushort(hb) << 16) | __bfloat16_as_ushort(ha);
    __nv_bfloat16 la = __float2bfloat16(a - __bfloat162float(ha));
    __nv_bfloat16 lb = __float2bfloat16(b - __bfloat162float(hb));
    uint32_t lo = ((uint32_t)__bfloat16_as_ushort(lb) << 16) | __bfloat16_as_ushort(la);
    *(uint32_t*)(Hi + elt) = hi;
    *(uint32_t*)(Lo + elt) = lo;
}

__device__ __forceinline__ float4 fmax4(float4 a, float4 b) {
    a.x = fmaxf(a.x, b.x); a.y = fmaxf(a.y, b.y);
    a.z = fmaxf(a.z, b.z); a.w = fmaxf(a.w, b.w);
    return a;
}

// ---------------- CSR build (3 launches) + weight pre-split ----------------
__global__ void hist_kernel(const int* __restrict__ dst,
                            const float* __restrict__ Wl, const float* __restrict__ Wr) {
    int e = blockIdx.x * blockDim.x + threadIdx.x;
    if (e < NE) atomicAdd(&g_counts[dst[e]], 1);
    if (e < NL * NF * NF) {
        float a = Wl[e];
        __nv_bfloat16 h = __float2bfloat16(a);
        g_WlHi[e] = __bfloat16_as_ushort(h);
        g_WlLo[e] = __bfloat16_as_ushort(__float2bfloat16(a - __bfloat162float(h)));
        float b = Wr[e];
        __nv_bfloat16 hb = __float2bfloat16(b);
        g_WrHi[e] = __bfloat16_as_ushort(hb);
        g_WrLo[e] = __bfloat16_as_ushort(__float2bfloat16(b - __bfloat162float(hb)));
    }
}

__global__ void scan_kernel() {
    __shared__ int s[1024];
    __shared__ int carry_s;
    int t = threadIdx.x;
    if (t == 0) carry_s = 0;
    __syncthreads();
    for (int base = 0; base < NN; base += 1024) {
        int c = carry_s;
        int i = base + t;
        int v = (i < NN) ? g_counts[i] : 0;
        if (i < NN) g_cursor[i] = 0;
        s[t] = v;
        __syncthreads();
#pragma unroll
        for (int d = 1; d < 1024; d <<= 1) {
            int add = (t >= d) ? s[t - d] : 0;
            __syncthreads();
            s[t] += add;
            __syncthreads();
        }
        int inc = s[t];
        if (i < NN) g_rowptr[i] = inc - v + c;     // exclusive
        if (t == 1023) carry_s = c + s[1023];
        __syncthreads();
    }
    if (t == 0) g_rowptr[NN] = NE;
}

__global__ void fill_kernel(const int* __restrict__ src, const int* __restrict__ dst) {
    int e = blockIdx.x * blockDim.x + threadIdx.x;
    if (e < NN) g_counts[e] = 0;
    if (e < NE) {
        int d = dst[e];
        int off = atomicAdd(&g_cursor[d], 1);
        g_col[g_rowptr[d] + off] = src[e];
    }
}

// ---------------- split x into h0 planes ----------------
__global__ void xsplit_kernel(const float* __restrict__ x,
                              uint16_t* __restrict__ Hi, uint16_t* __restrict__ Lo) {
    int idx = blockIdx.x * blockDim.x + threadIdx.x;   // per float4
    if (idx >= NN * 32) return;
    float4 v = ((const float4*)x)[idx];
    split4_store(Hi, Lo, idx, v);
}

// ---------------- max aggregation from planes, warp per node, MLP-8 ----------------
__global__ __launch_bounds__(256) void agg_kernel(
    const uint16_t* __restrict__ hHi, const uint16_t* __restrict__ hLo,
    uint16_t* __restrict__ aggHi, uint16_t* __restrict__ aggLo)
{
    int warp = (blockIdx.x * blockDim.x + threadIdx.x) >> 5;
    int lane = threadIdx.x & 31;
    if (warp >= NN) return;
    int beg = g_rowptr[warp];
    int end = g_rowptr[warp + 1];
    const uint2* H = (const uint2*)hHi;
    const uint2* L = (const uint2*)hLo;
    float4 m = make_float4(-FLT_MAX, -FLT_MAX, -FLT_MAX, -FLT_MAX);
    int e = beg;
    for (; e + 8 <= end; e += 8) {
        int s0 = g_col[e],     s1 = g_col[e + 1], s2 = g_col[e + 2], s3 = g_col[e + 3];
        int s4 = g_col[e + 4], s5 = g_col[e + 5], s6 = g_col[e + 6], s7 = g_col[e + 7];
        uint2 h0 = H[s0 * 32 + lane], l0 = L[s0 * 32 + lane];
        uint2 h1 = H[s1 * 32 + lane], l1 = L[s1 * 32 + lane];
        uint2 h2 = H[s2 * 32 + lane], l2 = L[s2 * 32 + lane];
        uint2 h3 = H[s3 * 32 + lane], l3 = L[s3 * 32 + lane];
        uint2 h4 = H[s4 * 32 + lane], l4 = L[s4 * 32 + lane];
        uint2 h5 = H[s5 * 32 + lane], l5 = L[s5 * 32 + lane];
        uint2 h6 = H[s6 * 32 + lane], l6 = L[s6 * 32 + lane];
        uint2 h7 = H[s7 * 32 + lane], l7 = L[s7 * 32 + lane];
        float4 v0 = rec4(h0, l0), v1 = rec4(h1, l1), v2 = rec4(h2, l2), v3 = rec4(h3, l3);
        float4 v4 = rec4(h4, l4), v5 = rec4(h5, l5), v6 = rec4(h6, l6), v7 = rec4(h7, l7);
        m = fmax4(m, fmax4(fmax4(fmax4(v0, v1), fmax4(v2, v3)),
                           fmax4(fmax4(v4, v5), fmax4(v6, v7))));
    }
    for (; e < end; e++) {
        int s = g_col[e];
        m = fmax4(m, rec4(H[s * 32 + lane], L[s * 32 + lane]));
    }
    if (beg == end) m = make_float4(0.f, 0.f, 0.f, 0.f);
    split4_store(aggHi, aggLo, warp * 32 + lane, m);
}

// ---------------- mma helpers ----------------
__device__ __forceinline__ uint32_t smem_u32(const void* p) {
    uint32_t a;
    asm("{ .reg .u64 t; cvta.to.shared.u64 t, %1; cvt.u32.u64 %0, t; }" : "=r"(a) : "l"(p));
    return a;
}

__device__ __forceinline__ void ldm4(uint32_t* r, uint32_t addr) {
    asm volatile("ldmatrix.sync.aligned.m8n8.x4.shared.b16 {%0,%1,%2,%3}, [%4];"
                 : "=r"(r[0]), "=r"(r[1]), "=r"(r[2]), "=r"(r[3]) : "r"(addr));
}

__device__ __forceinline__ void mma_bf16(float* d, const uint32_t* a, uint32_t b0, uint32_t b1) {
    asm volatile(
        "mma.sync.aligned.m16n8k16.row.col.f32.bf16.bf16.f32 "
        "{%0,%1,%2,%3}, {%4,%5,%6,%7}, {%8,%9}, {%0,%1,%2,%3};"
        : "+f"(d[0]), "+f"(d[1]), "+f"(d[2]), "+f"(d[3])
        : "r"(a[0]), "r"(a[1]), "r"(a[2]), "r"(a[3]), "r"(b0), "r"(b1));
}

// ================= bf16x3 tensor-core dual GEMM (plane-staged A) =================
#define A_STRIDE 272
#define SA_HI 0
#define SA_LO 34816
#define SB_HI 69632
#define SB_LO 87040
#define SM_TOT 104448

// stage one 64-n chunk of pre-split weights into sB
__device__ __forceinline__ void stage_w(char* smem, const uint16_t* __restrict__ WHi,
                                        const uint16_t* __restrict__ WLo, int nbase, int tid) {
#pragma unroll
    for (int i = 0; i < 4; i++) {
        int idx = tid + i * 256;         // 0..1023
        int nl = idx >> 4;               // 0..63
        int q  = idx & 15;               // uint4 within 128-k row
        const uint4* sh = (const uint4*)(WHi + (size_t)(nbase + nl) * NF);
        const uint4* sl = (const uint4*)(WLo + (size_t)(nbase + nl) * NF);
        *(uint4*)(smem + SB_HI + nl * A_STRIDE + q * 16) = sh[q];
        *(uint4*)(smem + SB_LO + nl * A_STRIDE + q * 16) = sl[q];
    }
}

// stage 128 A-rows from hi/lo planes: pure uint4 copies, no conversion
__device__ __forceinline__ void stage_A2(char* smem,
                                         const uint16_t* __restrict__ Hi,
                                         const uint16_t* __restrict__ Lo,
                                         int rowBase, int M, int tid) {
#pragma unroll
    for (int i = 0; i < 8; i++) {
        int idx = tid + i * 256;         // 0..2047
        int row = idx >> 4;              // 0..127
        int q   = idx & 15;              // uint4 within 128-elt row
        int gm  = rowBase + row;
        uint4 vh = make_uint4(0, 0, 0, 0), vl = make_uint4(0, 0, 0, 0);
        if (gm < M) {
            vh = ((const uint4*)(Hi + (size_t)gm * NF))[q];
            vl = ((const uint4*)(Lo + (size_t)gm * NF))[q];
        }
        *(uint4*)(smem + SA_HI + row * A_STRIDE + q * 16) = vh;
        *(uint4*)(smem + SA_LO + row * A_STRIDE + q * 16) = vl;
    }
}

// one K=128 sweep for one 64-n chunk: 3-pass bf16 split
__device__ __forceinline__ void mma_block(float acc[8][4],
                                          uint32_t aHiB, uint32_t aLoB,
                                          uint32_t bHiB, uint32_t bLoB) {
#pragma unroll
    for (int ks = 0; ks < 8; ks++) {
        uint32_t ko = ks * 32;
        uint32_t ah[4], al[4];
        ldm4(ah, aHiB + ko);
        ldm4(al, aLoB + ko);
#pragma unroll
        for (int p = 0; p < 4; p++) {
            uint32_t bh[4], blx[4];
            uint32_t po = (uint32_t)(p * 16 * A_STRIDE) + ko;
            ldm4(bh,  bHiB + po);
            ldm4(blx, bLoB + po);
            mma_bf16(acc[2 * p],     ah, bh[0],  bh[1]);
            mma_bf16(acc[2 * p],     ah, blx[0], blx[1]);
            mma_bf16(acc[2 * p],     al, bh[0],  bh[1]);
            mma_bf16(acc[2 * p + 1], ah, bh[2],  bh[3]);
            mma_bf16(acc[2 * p + 1], ah, blx[2], blx[3]);
            mma_bf16(acc[2 * p + 1], al, bh[2],  bh[3]);
        }
    }
}

__device__ __forceinline__ void run_half(
    char* smem,
    const uint16_t* __restrict__ AHi, const uint16_t* __restrict__ ALo,
    const uint16_t* __restrict__ WHi, const uint16_t* __restrict__ WLo,
    int rowBase, int M, int tid,
    float acc0[8][4], float acc1[8][4],
    uint32_t aHiB, uint32_t aLoB, uint32_t bHiB, uint32_t bLoB)
{
    stage_w(smem, WHi, WLo, 0, tid);
    stage_A2(smem, AHi, ALo, rowBase, M, tid);
    __syncthreads();
    mma_block(acc0, aHiB, aLoB, bHiB, bLoB);
    __syncthreads();
    stage_w(smem, WHi, WLo, 64, tid);
    __syncthreads();
    mma_block(acc1, aHiB, aLoB, bHiB, bLoB);
    __syncthreads();
}

__global__ __launch_bounds__(256, 2) void gemm_kernel(
    const uint16_t* __restrict__ aggHi, const uint16_t* __restrict__ aggLo,
    const uint16_t* __restrict__ hHi,   const uint16_t* __restrict__ hLo,
    const uint16_t* __restrict__ WlHi, const uint16_t* __restrict__ WlLo,
    const uint16_t* __restrict__ WrHi, const uint16_t* __restrict__ WrLo,
    const float* __restrict__ bias,
    uint16_t* __restrict__ CHi, uint16_t* __restrict__ CLo, int M)
{
    extern __shared__ char smem[];
    uint32_t su = smem_u32(smem);
    int tid = threadIdx.x;
    int lane = tid & 31;
    int wid = tid >> 5;
    int rowBase = blockIdx.x * 128;

    int lr = lane & 7, g = lane >> 3;
    uint32_t aOff = (uint32_t)((wid * 16 + lr + (g & 1) * 8) * A_STRIDE + (g >> 1) * 16);
    uint32_t bOff = (uint32_t)((lr + (g >> 1) * 8) * A_STRIDE + (g & 1) * 16);
    uint32_t aHiB = su + SA_HI + aOff, aLoB = su + SA_LO + aOff;
    uint32_t bHiB = su + SB_HI + bOff, bLoB = su + SB_LO + bOff;

    float acc0[8][4], acc1[8][4];
#pragma unroll
    for (int i = 0; i < 8; i++)
#pragma unroll
        for (int q = 0; q < 4; q++) { acc0[i][q] = 0.f; acc1[i][q] = 0.f; }

    run_half(smem, aggHi, aggLo, WlHi, WlLo, rowBase, M, tid, acc0, acc1, aHiB, aLoB, bHiB, bLoB);
    run_half(smem, hHi,   hLo,   WrHi, WrLo, rowBase, M, tid, acc0, acc1, aHiB, aLoB, bHiB, bLoB);

    // epilogue: bias + leaky, write split planes
    int r0 = rowBase + wid * 16 + (lane >> 2);
#pragma unroll
    for (int half = 0; half < 2; half++) {
        float (*A)[4] = half ? acc1 : acc0;
        int cbase = half * 64;
#pragma unroll
        for (int nt = 0; nt < 8; nt++) {
            int col = cbase + nt * 8 + 2 * (lane & 3);
            float b0 = bias[col], b1 = bias[col + 1];
            float v0 = A[nt][0] + b0;
            float v1 = A[nt][1] + b1;
            float v2 = A[nt][2] + b0;
            float v3 = A[nt][3] + b1;
            v0 = (v0 >= 0.f) ? v0 : SLOPE * v0;
            v1 = (v1 >= 0.f) ? v1 : SLOPE * v1;
            v2 = (v2 >= 0.f) ? v2 : SLOPE * v2;
            v3 = (v3 >= 0.f) ? v3 : SLOPE * v3;
            if (r0 < M)     split2_store(CHi, CLo, (size_t)r0 * NF + col, v0, v1);
            if (r0 + 8 < M) split2_store(CHi, CLo, (size_t)(r0 + 8) * NF + col, v2, v3);
        }
    }
}

// ---------------- fused final layer: gather max + 3-dim output ----------------
__global__ __launch_bounds__(256) void aggout_kernel(
    const uint16_t* __restrict__ hHi, const uint16_t* __restrict__ hLo,
    const float* __restrict__ Wl, const float* __restrict__ bl,
    const float* __restrict__ Wr, float* __restrict__ out)
{
    int warp = (blockIdx.x * blockDim.x + threadIdx.x) >> 5;
    int lane = threadIdx.x & 31;
    if (warp >= NN) return;
    const uint2* H = (const uint2*)hHi;
    const uint2* L = (const uint2*)hLo;
    int beg = g_rowptr[warp];
    int end = g_rowptr[warp + 1];
    float4 m = make_float4(-FLT_MAX, -FLT_MAX, -FLT_MAX, -FLT_MAX);
    int e = beg;
    for (; e + 8 <= end; e += 8) {
        int s0 = g_col[e],     s1 = g_col[e + 1], s2 = g_col[e + 2], s3 = g_col[e + 3];
        int s4 = g_col[e + 4], s5 = g_col[e + 5], s6 = g_col[e + 6], s7 = g_col[e + 7];
        float4 v0 = rec4(H[s0 * 32 + lane], L[s0 * 32 + lane]);
        float4 v1 = rec4(H[s1 * 32 + lane], L[s1 * 32 + lane]);
        float4 v2 = rec4(H[s2 * 32 + lane], L[s2 * 32 + lane]);
        float4 v3 = rec4(H[s3 * 32 + lane], L[s3 * 32 + lane]);
        float4 v4 = rec4(H[s4 * 32 + lane], L[s4 * 32 + lane]);
        float4 v5 = rec4(H[s5 * 32 + lane], L[s5 * 32 + lane]);
        float4 v6 = rec4(H[s6 * 32 + lane], L[s6 * 32 + lane]);
        float4 v7 = rec4(H[s7 * 32 + lane], L[s7 * 32 + lane]);
        m = fmax4(m, fmax4(fmax4(fmax4(v0, v1), fmax4(v2, v3)),
                           fmax4(fmax4(v4, v5), fmax4(v6, v7))));
    }
    for (; e < end; e++) {
        int s = g_col[e];
        m = fmax4(m, rec4(H[s * 32 + lane], L[s * 32 + lane]));
    }
    if (beg == end) m = make_float4(0.f, 0.f, 0.f, 0.f);

    float4 hv = rec4(H[warp * 32 + lane], L[warp * 32 + lane]);
#pragma unroll
    for (int o = 0; o < 3; o++) {
        float4 wl = ((const float4*)Wl)[o * 32 + lane];
        float4 wr = ((const float4*)Wr)[o * 32 + lane];
        float s = m.x * wl.x + m.y * wl.y + m.z * wl.z + m.w * wl.w
                + hv.x * wr.x + hv.y * wr.y + hv.z * wr.z + hv.w * wr.w;
#pragma unroll
        for (int off = 16; off; off >>= 1)
            s += __shfl_xor_sync(0xffffffff, s, off);
        if (lane == 0) out[warp * 3 + o] = tanhf(s + bl[o]) * 0.5f;
    }
}

// ---------------- host launcher ----------------
extern "C" void kernel_launch(void* const* d_in, const int* in_sizes, int n_in,
                              void* d_out, int out_size)
{
    const float* x      = (const float*)d_in[0];
    const int*   ei     = (const int*)d_in[1];
    const float* Wl     = (const float*)d_in[2];
    const float* bl     = (const float*)d_in[3];
    const float* Wr     = (const float*)d_in[4];
    const float* Wl_out = (const float*)d_in[5];
    const float* bl_out = (const float*)d_in[6];
    const float* Wr_out = (const float*)d_in[7];
    float* out = (float*)d_out;

    const int* src = ei;
    const int* dst = ei + NE;

    void *p0h, *p0l, *p1h, *p1l, *pah, *pal, *pWlHi, *pWlLo, *pWrHi, *pWrLo;
    cudaGetSymbolAddress(&p0h, g_h0Hi);
    cudaGetSymbolAddress(&p0l, g_h0Lo);
    cudaGetSymbolAddress(&p1h, g_h1Hi);
    cudaGetSymbolAddress(&p1l, g_h1Lo);
    cudaGetSymbolAddress(&pah, g_aggHi);
    cudaGetSymbolAddress(&pal, g_aggLo);
    cudaGetSymbolAddress(&pWlHi, g_WlHi);
    cudaGetSymbolAddress(&pWlLo, g_WlLo);
    cudaGetSymbolAddress(&pWrHi, g_WrHi);
    cudaGetSymbolAddress(&pWrLo, g_WrLo);
    uint16_t* hHi[2] = {(uint16_t*)p0h, (uint16_t*)p1h};
    uint16_t* hLo[2] = {(uint16_t*)p0l, (uint16_t*)p1l};
    uint16_t* aggHi = (uint16_t*)pah;
    uint16_t* aggLo = (uint16_t*)pal;
    uint16_t* wlHi = (uint16_t*)pWlHi;
    uint16_t* wlLo = (uint16_t*)pWlLo;
    uint16_t* wrHi = (uint16_t*)pWrHi;
    uint16_t* wrLo = (uint16_t*)pWrLo;

    cudaFuncSetAttribute(gemm_kernel, cudaFuncAttributeMaxDynamicSharedMemorySize, SM_TOT);

    // CSR build (3) + x split (1) -> launch #6 = gemm layer 0 (ncu captures #6)
    hist_kernel<<<(NE + 255) / 256, 256>>>(dst, Wl, Wr);
    scan_kernel<<<1, 1024>>>();
    fill_kernel<<<(NE + 255) / 256, 256>>>(src, dst);
    xsplit_kernel<<<(NN * 32 + 255) / 256, 256>>>(x, hHi[0], hLo[0]);

    const int AGG_BLOCKS  = (NN + 7) / 8;
    const int GEMM_BLOCKS = (NN + 127) / 128;

    int cur = 0;
    for (int i = 0; i < NL; i++) {
        agg_kernel<<<AGG_BLOCKS, 256>>>(hHi[cur], hLo[cur], aggHi, aggLo);
        int nxt = cur ^ 1;
        gemm_kernel<<<GEMM_BLOCKS, 256, SM_TOT>>>(
            aggHi, aggLo, hHi[cur], hLo[cur],
            wlHi + (size_t)i * NF * NF, wlLo + (size_t)i * NF * NF,
            wrHi + (size_t)i * NF * NF, wrLo + (size_t)i * NF * NF,
            bl + i * NF, hHi[nxt], hLo[nxt], NN);
        cur = nxt;
    }

    // fused final aggregation + output conv
    aggout_kernel<<<AGG_BLOCKS, 256>>>(hHi[cur], hLo[cur], Wl_out, bl_out, Wr_out, out);
}

// round 9
// speedup vs baseline: 1.1107x; 1.1107x over previous
#include <cuda_runtime.h>
#include <cuda_bf16.h>
#include <math.h>
#include <float.h>
#include <stdint.h>

// Problem constants (match reference)
#define NN 100000
#define NE 1600000
#define NF 128
#define NL 7
#define SLOPE 0.02f

// ---------------- device scratch (static, no allocation) ----------------
// zero-initialized at load; g_counts re-zeroed by fill_kernel, g_cursor by
// scan_kernel each call -> deterministic across calls.
__device__ int   g_counts[NN];
__device__ int   g_cursor[NN];
__device__ int   g_rowptr[NN + 1];
__device__ int   g_col[NE];
// fp32 activations (gather-side)
__device__ __align__(16) float g_hf0[NN * NF];
__device__ __align__(16) float g_hf1[NN * NF];
// split bf16 planes (gemm-side)
__device__ __align__(16) uint16_t g_hp0Hi[NN * NF];
__device__ __align__(16) uint16_t g_hp0Lo[NN * NF];
__device__ __align__(16) uint16_t g_hp1Hi[NN * NF];
__device__ __align__(16) uint16_t g_hp1Lo[NN * NF];
__device__ __align__(16) uint16_t g_aggHi[NN * NF];
__device__ __align__(16) uint16_t g_aggLo[NN * NF];
// pre-split weights: hi/lo bf16, layout [l][n][k] (same as input W)
__device__ __align__(16) uint16_t g_WlHi[NL * NF * NF];
__device__ __align__(16) uint16_t g_WlLo[NL * NF * NF];
__device__ __align__(16) uint16_t g_WrHi[NL * NF * NF];
__device__ __align__(16) uint16_t g_WrLo[NL * NF * NF];

// ---------------- split helpers ----------------
__device__ __forceinline__ void split4_store(uint16_t* __restrict__ Hi,
                                             uint16_t* __restrict__ Lo,
                                             int idx4, float4 v) {
    __nv_bfloat16 hx = __float2bfloat16(v.x);
    __nv_bfloat16 hy = __float2bfloat16(v.y);
    __nv_bfloat16 hz = __float2bfloat16(v.z);
    __nv_bfloat16 hw = __float2bfloat16(v.w);
    uint32_t hi01 = ((uint32_t)__bfloat16_as_ushort(hy) << 16) | __bfloat16_as_ushort(hx);
    uint32_t hi23 = ((uint32_t)__bfloat16_as_ushort(hw) << 16) | __bfloat16_as_ushort(hz);
    __nv_bfloat16 lx = __float2bfloat16(v.x - __bfloat162float(hx));
    __nv_bfloat16 ly = __float2bfloat16(v.y - __bfloat162float(hy));
    __nv_bfloat16 lz = __float2bfloat16(v.z - __bfloat162float(hz));
    __nv_bfloat16 lw = __float2bfloat16(v.w - __bfloat162float(hw));
    uint32_t lo01 = ((uint32_t)__bfloat16_as_ushort(ly) << 16) | __bfloat16_as_ushort(lx);
    uint32_t lo23 = ((uint32_t)__bfloat16_as_ushort(lw) << 16) | __bfloat16_as_ushort(lz);
    ((uint2*)Hi)[idx4] = make_uint2(hi01, hi23);
    ((uint2*)Lo)[idx4] = make_uint2(lo01, lo23);
}

__device__ __forceinline__ void split2_store(uint16_t* __restrict__ Hi,
                                             uint16_t* __restrict__ Lo,
                                             size_t elt, float a, float b) {
    __nv_bfloat16 ha = __float2bfloat16(a), hb = __float2bfloat16(b);
    uint32_t hi = ((uint32_t)__bfloat16_as_ushort(hb) << 16) | __bfloat16_as_ushort(ha);
    __nv_bfloat16 la = __float2bfloat16(a - __bfloat162float(ha));
    __nv_bfloat16 lb = __float2bfloat16(b - __bfloat162float(hb));
    uint32_t lo = ((uint32_t)__bfloat16_as_ushort(lb) << 16) | __bfloat16_as_ushort(la);
    *(uint32_t*)(Hi + elt) = hi;
    *(uint32_t*)(Lo + elt) = lo;
}

__device__ __forceinline__ float4 fmax4(float4 a, float4 b) {
    a.x = fmaxf(a.x, b.x); a.y = fmaxf(a.y, b.y);
    a.z = fmaxf(a.z, b.z); a.w = fmaxf(a.w, b.w);
    return a;
}

// ---------------- CSR build (3 launches) + weight pre-split ----------------
__global__ void hist_kernel(const int* __restrict__ dst,
                            const float* __restrict__ Wl, const float* __restrict__ Wr) {
    int e = blockIdx.x * blockDim.x + threadIdx.x;
    if (e < NE) atomicAdd(&g_counts[dst[e]], 1);
    if (e < NL * NF * NF) {
        float a = Wl[e];
        __nv_bfloat16 h = __float2bfloat16(a);
        g_WlHi[e] = __bfloat16_as_ushort(h);
        g_WlLo[e] = __bfloat16_as_ushort(__float2bfloat16(a - __bfloat162float(h)));
        float b = Wr[e];
        __nv_bfloat16 hb = __float2bfloat16(b);
        g_WrHi[e] = __bfloat16_as_ushort(hb);
        g_WrLo[e] = __bfloat16_as_ushort(__float2bfloat16(b - __bfloat162float(hb)));
    }
}

__global__ void scan_kernel() {
    __shared__ int s[1024];
    __shared__ int carry_s;
    int t = threadIdx.x;
    if (t == 0) carry_s = 0;
    __syncthreads();
    for (int base = 0; base < NN; base += 1024) {
        int c = carry_s;
        int i = base + t;
        int v = (i < NN) ? g_counts[i] : 0;
        if (i < NN) g_cursor[i] = 0;
        s[t] = v;
        __syncthreads();
#pragma unroll
        for (int d = 1; d < 1024; d <<= 1) {
            int add = (t >= d) ? s[t - d] : 0;
            __syncthreads();
            s[t] += add;
            __syncthreads();
        }
        int inc = s[t];
        if (i < NN) g_rowptr[i] = inc - v + c;     // exclusive
        if (t == 1023) carry_s = c + s[1023];
        __syncthreads();
    }
    if (t == 0) g_rowptr[NN] = NE;
}

__global__ void fill_kernel(const int* __restrict__ src, const int* __restrict__ dst) {
    int e = blockIdx.x * blockDim.x + threadIdx.x;
    if (e < NN) g_counts[e] = 0;
    if (e < NE) {
        int d = dst[e];
        int off = atomicAdd(&g_cursor[d], 1);
        g_col[g_rowptr[d] + off] = src[e];
    }
}

// ---------------- split x into plane pair 0 ----------------
__global__ void xsplit_kernel(const float* __restrict__ x,
                              uint16_t* __restrict__ Hi, uint16_t* __restrict__ Lo) {
    int idx = blockIdx.x * blockDim.x + threadIdx.x;   // per float4
    if (idx >= NN * 32) return;
    float4 v = ((const float4*)x)[idx];
    split4_store(Hi, Lo, idx, v);
}

// ---------------- max aggregation: fp32 gather, plane output ----------------
__global__ __launch_bounds__(256) void agg_kernel(const float* __restrict__ h,
                                                  uint16_t* __restrict__ aggHi,
                                                  uint16_t* __restrict__ aggLo) {
    int warp = (blockIdx.x * blockDim.x + threadIdx.x) >> 5;
    int lane = threadIdx.x & 31;
    if (warp >= NN) return;
    int beg = g_rowptr[warp];
    int end = g_rowptr[warp + 1];
    const float4* h4 = (const float4*)h;
    float4 m = make_float4(-FLT_MAX, -FLT_MAX, -FLT_MAX, -FLT_MAX);
    int e = beg;
    for (; e + 8 <= end; e += 8) {
        float4 v0 = h4[g_col[e]     * 32 + lane];
        float4 v1 = h4[g_col[e + 1] * 32 + lane];
        float4 v2 = h4[g_col[e + 2] * 32 + lane];
        float4 v3 = h4[g_col[e + 3] * 32 + lane];
        float4 v4 = h4[g_col[e + 4] * 32 + lane];
        float4 v5 = h4[g_col[e + 5] * 32 + lane];
        float4 v6 = h4[g_col[e + 6] * 32 + lane];
        float4 v7 = h4[g_col[e + 7] * 32 + lane];
        m = fmax4(m, fmax4(fmax4(fmax4(v0, v1), fmax4(v2, v3)),
                           fmax4(fmax4(v4, v5), fmax4(v6, v7))));
    }
    for (; e < end; e++) m = fmax4(m, h4[g_col[e] * 32 + lane]);
    if (beg == end) m = make_float4(0.f, 0.f, 0.f, 0.f);
    split4_store(aggHi, aggLo, warp * 32 + lane, m);
}

// ---------------- mma helpers ----------------
__device__ __forceinline__ uint32_t smem_u32(const void* p) {
    uint32_t a;
    asm("{ .reg .u64 t; cvta.to.shared.u64 t, %1; cvt.u32.u64 %0, t; }" : "=r"(a) : "l"(p));
    return a;
}

__device__ __forceinline__ void ldm4(uint32_t* r, uint32_t addr) {
    asm volatile("ldmatrix.sync.aligned.m8n8.x4.shared.b16 {%0,%1,%2,%3}, [%4];"
                 : "=r"(r[0]), "=r"(r[1]), "=r"(r[2]), "=r"(r[3]) : "r"(addr));
}

__device__ __forceinline__ void mma_bf16(float* d, const uint32_t* a, uint32_t b0, uint32_t b1) {
    asm volatile(
        "mma.sync.aligned.m16n8k16.row.col.f32.bf16.bf16.f32 "
        "{%0,%1,%2,%3}, {%4,%5,%6,%7}, {%8,%9}, {%0,%1,%2,%3};"
        : "+f"(d[0]), "+f"(d[1]), "+f"(d[2]), "+f"(d[3])
        : "r"(a[0]), "r"(a[1]), "r"(a[2]), "r"(a[3]), "r"(b0), "r"(b1));
}

__device__ __forceinline__ void cp16(uint32_t d, const void* s) {
    asm volatile("cp.async.cg.shared.global [%0], [%1], 16;" :: "r"(d), "l"(s));
}

// ================= bf16x3 dual GEMM: M-tile 64, full-N B, 3 barriers =================
#define A_STRIDE 272
#define SA_HI 0
#define SA_LO 17408
#define SB_HI 34816
#define SB_LO 69632
#define SM_TOT 104448

// stage A (64 rows from planes) + B (full 128 n-rows from split W) via cp.async
__device__ __forceinline__ void stage(char* smem, uint32_t su,
    const uint16_t* __restrict__ AHi, const uint16_t* __restrict__ ALo,
    const uint16_t* __restrict__ WHi, const uint16_t* __restrict__ WLo,
    int rowBase, int M, int tid)
{
    // A: 2 planes x 64 rows x 16 uint4
#pragma unroll
    for (int i = 0; i < 8; i++) {
        int idx = tid + i * 256;
        int plane = idx >> 10;
        int rem = idx & 1023;
        int row = rem >> 4;
        int q   = rem & 15;
        int gm  = rowBase + row;
        uint32_t dst = su + (plane ? SA_LO : SA_HI) + row * A_STRIDE + q * 16;
        if (gm < M) {
            const uint16_t* s = (plane ? ALo : AHi) + (size_t)gm * NF + q * 8;
            cp16(dst, s);
        } else {
            *(uint4*)(smem + (plane ? SA_LO : SA_HI) + row * A_STRIDE + q * 16) =
                make_uint4(0, 0, 0, 0);
        }
    }
    // B: 2 planes x 128 rows x 16 uint4
#pragma unroll
    for (int i = 0; i < 16; i++) {
        int idx = tid + i * 256;
        int plane = idx >> 11;
        int rem = idx & 2047;
        int nl = rem >> 4;
        int q  = rem & 15;
        uint32_t dst = su + (plane ? SB_LO : SB_HI) + nl * A_STRIDE + q * 16;
        const uint16_t* s = (plane ? WLo : WHi) + (size_t)nl * NF + q * 8;
        cp16(dst, s);
    }
    asm volatile("cp.async.commit_group;" ::: "memory");
    asm volatile("cp.async.wait_group 0;" ::: "memory");
}

// full K=128 sweep over this warp's 16 rows x 64 cols, 3-pass bf16 split
__device__ __forceinline__ void mma_half(float acc[8][4],
                                         uint32_t aHiB, uint32_t aLoB,
                                         uint32_t bHiB, uint32_t bLoB) {
#pragma unroll
    for (int ks = 0; ks < 8; ks++) {
        uint32_t ko = ks * 32;
        uint32_t ah[4], al[4];
        ldm4(ah, aHiB + ko);
        ldm4(al, aLoB + ko);
#pragma unroll
        for (int p = 0; p < 4; p++) {
            uint32_t bh[4], blx[4];
            uint32_t po = (uint32_t)(p * 16 * A_STRIDE) + ko;
            ldm4(bh,  bHiB + po);
            ldm4(blx, bLoB + po);
            mma_bf16(acc[2 * p],     ah, bh[0],  bh[1]);
            mma_bf16(acc[2 * p],     ah, blx[0], blx[1]);
            mma_bf16(acc[2 * p],     al, bh[0],  bh[1]);
            mma_bf16(acc[2 * p + 1], ah, bh[2],  bh[3]);
            mma_bf16(acc[2 * p + 1], ah, blx[2], blx[3]);
            mma_bf16(acc[2 * p + 1], al, bh[2],  bh[3]);
        }
    }
}

__global__ __launch_bounds__(256, 2) void gemm_kernel(
    const uint16_t* __restrict__ aggHi, const uint16_t* __restrict__ aggLo,
    const uint16_t* __restrict__ hHi,   const uint16_t* __restrict__ hLo,
    const uint16_t* __restrict__ WlHi, const uint16_t* __restrict__ WlLo,
    const uint16_t* __restrict__ WrHi, const uint16_t* __restrict__ WrLo,
    const float* __restrict__ bias,
    float* __restrict__ Cf, uint16_t* __restrict__ CHi, uint16_t* __restrict__ CLo, int M)
{
    extern __shared__ char smem[];
    uint32_t su = smem_u32(smem);
    int tid = threadIdx.x;
    int lane = tid & 31;
    int wid = tid >> 5;
    int wm = wid & 3;        // 4 M-groups x 16 rows
    int wn = wid >> 2;       // 2 N-groups x 64 cols
    int rowBase = blockIdx.x * 64;

    int lr = lane & 7, g = lane >> 3;
    uint32_t aOff = (uint32_t)((wm * 16 + lr + (g & 1) * 8) * A_STRIDE + (g >> 1) * 16);
    uint32_t bOff = (uint32_t)((wn * 64 + lr + (g >> 1) * 8) * A_STRIDE + (g & 1) * 16);
    uint32_t aHiB = su + SA_HI + aOff, aLoB = su + SA_LO + aOff;
    uint32_t bHiB = su + SB_HI + bOff, bLoB = su + SB_LO + bOff;

    float acc[8][4];
#pragma unroll
    for (int i = 0; i < 8; i++)
#pragma unroll
        for (int q = 0; q < 4; q++) acc[i][q] = 0.f;

    // half 0: A = agg planes, B = Wl
    stage(smem, su, aggHi, aggLo, WlHi, WlLo, rowBase, M, tid);
    __syncthreads();
    mma_half(acc, aHiB, aLoB, bHiB, bLoB);
    __syncthreads();
    // half 1: A = h planes, B = Wr
    stage(smem, su, hHi, hLo, WrHi, WrLo, rowBase, M, tid);
    __syncthreads();
    mma_half(acc, aHiB, aLoB, bHiB, bLoB);

    // epilogue: bias + leaky; write fp32 + split planes
    int r0 = rowBase + wm * 16 + (lane >> 2);
#pragma unroll
    for (int nt = 0; nt < 8; nt++) {
        int col = wn * 64 + nt * 8 + 2 * (lane & 3);
        float b0 = bias[col], b1 = bias[col + 1];
        float v0 = acc[nt][0] + b0;
        float v1 = acc[nt][1] + b1;
        float v2 = acc[nt][2] + b0;
        float v3 = acc[nt][3] + b1;
        v0 = (v0 >= 0.f) ? v0 : SLOPE * v0;
        v1 = (v1 >= 0.f) ? v1 : SLOPE * v1;
        v2 = (v2 >= 0.f) ? v2 : SLOPE * v2;
        v3 = (v3 >= 0.f) ? v3 : SLOPE * v3;
        if (r0 < M) {
            size_t e = (size_t)r0 * NF + col;
            *((float2*)&Cf[e]) = make_float2(v0, v1);
            split2_store(CHi, CLo, e, v0, v1);
        }
        if (r0 + 8 < M) {
            size_t e = (size_t)(r0 + 8) * NF + col;
            *((float2*)&Cf[e]) = make_float2(v2, v3);
            split2_store(CHi, CLo, e, v2, v3);
        }
    }
}

// ---------------- fused final layer: fp32 gather max + 3-dim output ----------------
__global__ __launch_bounds__(256) void aggout_kernel(
    const float* __restrict__ h,
    const float* __restrict__ Wl, const float* __restrict__ bl,
    const float* __restrict__ Wr, float* __restrict__ out)
{
    int warp = (blockIdx.x * blockDim.x + threadIdx.x) >> 5;
    int lane = threadIdx.x & 31;
    if (warp >= NN) return;
    const float4* h4 = (const float4*)h;
    int beg = g_rowptr[warp];
    int end = g_rowptr[warp + 1];
    float4 m = make_float4(-FLT_MAX, -FLT_MAX, -FLT_MAX, -FLT_MAX);
    int e = beg;
    for (; e + 8 <= end; e += 8) {
        float4 v0 = h4[g_col[e]     * 32 + lane];
        float4 v1 = h4[g_col[e + 1] * 32 + lane];
        float4 v2 = h4[g_col[e + 2] * 32 + lane];
        float4 v3 = h4[g_col[e + 3] * 32 + lane];
        float4 v4 = h4[g_col[e + 4] * 32 + lane];
        float4 v5 = h4[g_col[e + 5] * 32 + lane];
        float4 v6 = h4[g_col[e + 6] * 32 + lane];
        float4 v7 = h4[g_col[e + 7] * 32 + lane];
        m = fmax4(m, fmax4(fmax4(fmax4(v0, v1), fmax4(v2, v3)),
                           fmax4(fmax4(v4, v5), fmax4(v6, v7))));
    }
    for (; e < end; e++) m = fmax4(m, h4[g_col[e] * 32 + lane]);
    if (beg == end) m = make_float4(0.f, 0.f, 0.f, 0.f);

    float4 hv = h4[warp * 32 + lane];
#pragma unroll
    for (int o = 0; o < 3; o++) {
        float4 wl = ((const float4*)Wl)[o * 32 + lane];
        float4 wr = ((const float4*)Wr)[o * 32 + lane];
        float s = m.x * wl.x + m.y * wl.y + m.z * wl.z + m.w * wl.w
                + hv.x * wr.x + hv.y * wr.y + hv.z * wr.z + hv.w * wr.w;
#pragma unroll
        for (int off = 16; off; off >>= 1)
            s += __shfl_xor_sync(0xffffffff, s, off);
        if (lane == 0) out[warp * 3 + o] = tanhf(s + bl[o]) * 0.5f;
    }
}

// ---------------- host launcher ----------------
extern "C" void kernel_launch(void* const* d_in, const int* in_sizes, int n_in,
                              void* d_out, int out_size)
{
    const float* x      = (const float*)d_in[0];
    const int*   ei     = (const int*)d_in[1];
    const float* Wl     = (const float*)d_in[2];
    const float* bl     = (const float*)d_in[3];
    const float* Wr     = (const float*)d_in[4];
    const float* Wl_out = (const float*)d_in[5];
    const float* bl_out = (const float*)d_in[6];
    const float* Wr_out = (const float*)d_in[7];
    float* out = (float*)d_out;

    const int* src = ei;
    const int* dst = ei + NE;

    void *pf0, *pf1, *p0h, *p0l, *p1h, *p1l, *pah, *pal, *pWlHi, *pWlLo, *pWrHi, *pWrLo;
    cudaGetSymbolAddress(&pf0, g_hf0);
    cudaGetSymbolAddress(&pf1, g_hf1);
    cudaGetSymbolAddress(&p0h, g_hp0Hi);
    cudaGetSymbolAddress(&p0l, g_hp0Lo);
    cudaGetSymbolAddress(&p1h, g_hp1Hi);
    cudaGetSymbolAddress(&p1l, g_hp1Lo);
    cudaGetSymbolAddress(&pah, g_aggHi);
    cudaGetSymbolAddress(&pal, g_aggLo);
    cudaGetSymbolAddress(&pWlHi, g_WlHi);
    cudaGetSymbolAddress(&pWlLo, g_WlLo);
    cudaGetSymbolAddress(&pWrHi, g_WrHi);
    cudaGetSymbolAddress(&pWrLo, g_WrLo);
    float* hf[2]     = {(float*)pf0, (float*)pf1};
    uint16_t* hpHi[2] = {(uint16_t*)p0h, (uint16_t*)p1h};
    uint16_t* hpLo[2] = {(uint16_t*)p0l, (uint16_t*)p1l};
    uint16_t* aggHi = (uint16_t*)pah;
    uint16_t* aggLo = (uint16_t*)pal;
    uint16_t* wlHi = (uint16_t*)pWlHi;
    uint16_t* wlLo = (uint16_t*)pWlLo;
    uint16_t* wrHi = (uint16_t*)pWrHi;
    uint16_t* wrLo = (uint16_t*)pWrLo;

    cudaFuncSetAttribute(gemm_kernel, cudaFuncAttributeMaxDynamicSharedMemorySize, SM_TOT);

    // CSR build (3) + x split (1) -> launch #6 = gemm layer 0 (ncu captures #6)
    hist_kernel<<<(NE + 255) / 256, 256>>>(dst, Wl, Wr);
    scan_kernel<<<1, 1024>>>();
    fill_kernel<<<(NE + 255) / 256, 256>>>(src, dst);
    xsplit_kernel<<<(NN * 32 + 255) / 256, 256>>>(x, hpHi[0], hpLo[0]);

    const int AGG_BLOCKS  = (NN + 7) / 8;
    const int GEMM_BLOCKS = (NN + 63) / 64;

    const float* curF = x;
    int cur = 0;
    for (int i = 0; i < NL; i++) {
        agg_kernel<<<AGG_BLOCKS, 256>>>(curF, aggHi, aggLo);
        int nxt = cur ^ 1;
        gemm_kernel<<<GEMM_BLOCKS, 256, SM_TOT>>>(
            aggHi, aggLo, hpHi[cur], hpLo[cur],
            wlHi + (size_t)i * NF * NF, wlLo + (size_t)i * NF * NF,
            wrHi + (size_t)i * NF * NF, wrLo + (size_t)i * NF * NF,
            bl + i * NF, hf[nxt], hpHi[nxt], hpLo[nxt], NN);
        curF = hf[nxt];
        cur = nxt;
    }

    // fused final aggregation + output conv (fp32 gather)
    aggout_kernel<<<AGG_BLOCKS, 256>>>(curF, Wl_out, bl_out, Wr_out, out);
}

// round 10
// speedup vs baseline: 1.1677x; 1.0513x over previous
#include <cuda_runtime.h>
#include <cuda_bf16.h>
#include <math.h>
#include <float.h>
#include <stdint.h>

// Problem constants (match reference)
#define NN 100000
#define NE 1600000
#define NF 128
#define NL 7
#define SLOPE 0.02f

// ---------------- device scratch (static, no allocation) ----------------
// zero-initialized at load; g_counts re-zeroed by fill_kernel, g_cursor by
// scan_kernel each call -> deterministic across calls.
__device__ int   g_counts[NN];
__device__ int   g_cursor[NN];
__device__ int   g_rowptr[NN + 1];
__device__ int   g_col[NE];
__device__ __align__(16) float g_h0[NN * NF];
__device__ __align__(16) float g_h1[NN * NF];
__device__ __align__(16) float g_agg[NN * NF];
// pre-split weights: hi/lo bf16, layout [l][n][k] (same as input W)
__device__ __align__(16) uint16_t g_WlHi[NL * NF * NF];
__device__ __align__(16) uint16_t g_WlLo[NL * NF * NF];
__device__ __align__(16) uint16_t g_WrHi[NL * NF * NF];
__device__ __align__(16) uint16_t g_WrLo[NL * NF * NF];

// ---------------- CSR build (3 launches) + weight pre-split ----------------
__global__ void hist_kernel(const int* __restrict__ dst,
                            const float* __restrict__ Wl, const float* __restrict__ Wr) {
    int e = blockIdx.x * blockDim.x + threadIdx.x;
    if (e < NE) atomicAdd(&g_counts[dst[e]], 1);
    if (e < NL * NF * NF) {
        float a = Wl[e];
        __nv_bfloat16 h = __float2bfloat16(a);
        g_WlHi[e] = __bfloat16_as_ushort(h);
        g_WlLo[e] = __bfloat16_as_ushort(__float2bfloat16(a - __bfloat162float(h)));
        float b = Wr[e];
        __nv_bfloat16 hb = __float2bfloat16(b);
        g_WrHi[e] = __bfloat16_as_ushort(hb);
        g_WrLo[e] = __bfloat16_as_ushort(__float2bfloat16(b - __bfloat162float(hb)));
    }
}

__global__ void scan_kernel() {
    __shared__ int s[1024];
    __shared__ int carry_s;
    int t = threadIdx.x;
    if (t == 0) carry_s = 0;
    __syncthreads();
    for (int base = 0; base < NN; base += 1024) {
        int c = carry_s;
        int i = base + t;
        int v = (i < NN) ? g_counts[i] : 0;
        if (i < NN) g_cursor[i] = 0;
        s[t] = v;
        __syncthreads();
#pragma unroll
        for (int d = 1; d < 1024; d <<= 1) {
            int add = (t >= d) ? s[t - d] : 0;
            __syncthreads();
            s[t] += add;
            __syncthreads();
        }
        int inc = s[t];
        if (i < NN) g_rowptr[i] = inc - v + c;     // exclusive
        if (t == 1023) carry_s = c + s[1023];
        __syncthreads();
    }
    if (t == 0) g_rowptr[NN] = NE;
}

__global__ void fill_kernel(const int* __restrict__ src, const int* __restrict__ dst) {
    int e = blockIdx.x * blockDim.x + threadIdx.x;
    if (e < NN) g_counts[e] = 0;
    if (e < NE) {
        int d = dst[e];
        int off = atomicAdd(&g_cursor[d], 1);
        g_col[g_rowptr[d] + off] = src[e];
    }
}

// ---------------- helpers ----------------
__device__ __forceinline__ float4 fmax4(float4 a, float4 b) {
    a.x = fmaxf(a.x, b.x); a.y = fmaxf(a.y, b.y);
    a.z = fmaxf(a.z, b.z); a.w = fmaxf(a.w, b.w);
    return a;
}

__device__ __forceinline__ uint32_t smem_u32(const void* p) {
    uint32_t a;
    asm("{ .reg .u64 t; cvta.to.shared.u64 t, %1; cvt.u32.u64 %0, t; }" : "=r"(a) : "l"(p));
    return a;
}

__device__ __forceinline__ void ldm4(uint32_t* r, uint32_t addr) {
    asm volatile("ldmatrix.sync.aligned.m8n8.x4.shared.b16 {%0,%1,%2,%3}, [%4];"
                 : "=r"(r[0]), "=r"(r[1]), "=r"(r[2]), "=r"(r[3]) : "r"(addr));
}

__device__ __forceinline__ void mma_bf16(float* d, const uint32_t* a, uint32_t b0, uint32_t b1) {
    asm volatile(
        "mma.sync.aligned.m16n8k16.row.col.f32.bf16.bf16.f32 "
        "{%0,%1,%2,%3}, {%4,%5,%6,%7}, {%8,%9}, {%0,%1,%2,%3};"
        : "+f"(d[0]), "+f"(d[1]), "+f"(d[2]), "+f"(d[3])
        : "r"(a[0]), "r"(a[1]), "r"(a[2]), "r"(a[3]), "r"(b0), "r"(b1));
}

__device__ __forceinline__ void cp16(uint32_t d, const void* s) {
    asm volatile("cp.async.cg.shared.global [%0], [%1], 16;" :: "r"(d), "l"(s));
}

// ---------------- standalone max aggregation: warp per node, MLP-8 ----------------
__global__ __launch_bounds__(256) void agg_kernel(const float* __restrict__ h,
                                                  float* __restrict__ agg) {
    int warp = (blockIdx.x * blockDim.x + threadIdx.x) >> 5;
    int lane = threadIdx.x & 31;
    if (warp >= NN) return;
    int beg = g_rowptr[warp];
    int end = g_rowptr[warp + 1];
    const float4* h4 = (const float4*)h;
    float4 m = make_float4(-FLT_MAX, -FLT_MAX, -FLT_MAX, -FLT_MAX);
    int e = beg;
    for (; e + 8 <= end; e += 8) {
        float4 v0 = h4[g_col[e]     * 32 + lane];
        float4 v1 = h4[g_col[e + 1] * 32 + lane];
        float4 v2 = h4[g_col[e + 2] * 32 + lane];
        float4 v3 = h4[g_col[e + 3] * 32 + lane];
        float4 v4 = h4[g_col[e + 4] * 32 + lane];
        float4 v5 = h4[g_col[e + 5] * 32 + lane];
        float4 v6 = h4[g_col[e + 6] * 32 + lane];
        float4 v7 = h4[g_col[e + 7] * 32 + lane];
        m = fmax4(m, fmax4(fmax4(fmax4(v0, v1), fmax4(v2, v3)),
                           fmax4(fmax4(v4, v5), fmax4(v6, v7))));
    }
    for (; e < end; e++) m = fmax4(m, h4[g_col[e] * 32 + lane]);
    if (beg == end) m = make_float4(0.f, 0.f, 0.f, 0.f);
    ((float4*)agg)[warp * 32 + lane] = m;
}

// ================= pipelined bf16x3 dual GEMM (M=64, W double-buffered) =================
// C[M,128] = A0@Wl^T + A1@Wr^T + bias, then leaky.
#define A_STRIDE 272
#define SA_HI   0
#define SA_LO   17408
#define SW_BASE 34816            // 2 W buffers x (HI,LO) planes of 17408B each
#define SW_BUF  34816            // stride between buffers
#define SM_TOT  104448

// split fp32 float4 into hi/lo bf16, write to A planes at (row, q)
__device__ __forceinline__ void write_splitA(char* smem, int row, int q, float4 v) {
    __nv_bfloat16 hx = __float2bfloat16(v.x);
    __nv_bfloat16 hy = __float2bfloat16(v.y);
    __nv_bfloat16 hz = __float2bfloat16(v.z);
    __nv_bfloat16 hw = __float2bfloat16(v.w);
    uint32_t hi01 = ((uint32_t)__bfloat16_as_ushort(hy) << 16) | __bfloat16_as_ushort(hx);
    uint32_t hi23 = ((uint32_t)__bfloat16_as_ushort(hw) << 16) | __bfloat16_as_ushort(hz);
    __nv_bfloat16 lx = __float2bfloat16(v.x - __bfloat162float(hx));
    __nv_bfloat16 ly = __float2bfloat16(v.y - __bfloat162float(hy));
    __nv_bfloat16 lz = __float2bfloat16(v.z - __bfloat162float(hz));
    __nv_bfloat16 lw = __float2bfloat16(v.w - __bfloat162float(hw));
    uint32_t lo01 = ((uint32_t)__bfloat16_as_ushort(ly) << 16) | __bfloat16_as_ushort(lx);
    uint32_t lo23 = ((uint32_t)__bfloat16_as_ushort(lw) << 16) | __bfloat16_as_ushort(lz);
    uint32_t off = (uint32_t)(row * A_STRIDE + q * 8);
    *(uint2*)(smem + SA_HI + off) = make_uint2(hi01, hi23);
    *(uint2*)(smem + SA_LO + off) = make_uint2(lo01, lo23);
}

// async-load one 64-n W chunk (both planes) into buffer b
__device__ __forceinline__ void stage_w_async(uint32_t su,
    const uint16_t* __restrict__ WHi, const uint16_t* __restrict__ WLo,
    int nbase, int buf, int tid)
{
    uint32_t base = su + SW_BASE + buf * SW_BUF;
#pragma unroll
    for (int i = 0; i < 8; i++) {
        int idx = tid + i * 256;         // 0..2047
        int plane = idx >> 10;
        int rem = idx & 1023;
        int nl = rem >> 4;               // 0..63
        int q  = rem & 15;
        uint32_t dst = base + plane * 17408 + nl * A_STRIDE + q * 16;
        const uint16_t* s = (plane ? WLo : WHi) + (size_t)(nbase + nl) * NF + q * 8;
        cp16(dst, s);
    }
    asm volatile("cp.async.commit_group;" ::: "memory");
}

// stage 64 A-rows (fp32 -> split bf16 planes), synchronous
__device__ __forceinline__ void stage_A(char* smem, const float* __restrict__ src,
                                        int rowBase, int M, int tid) {
    const float4* s4 = (const float4*)src;
#pragma unroll
    for (int i = 0; i < 8; i++) {
        int idx = tid + i * 256;         // 0..2047
        int row = idx >> 5;              // 0..63
        int q   = idx & 31;
        int gm  = rowBase + row;
        float4 v = make_float4(0.f, 0.f, 0.f, 0.f);
        if (gm < M) v = s4[gm * 32 + q];
        write_splitA(smem, row, q, v);
    }
}

// K=128 sweep over one 64-col chunk; 3-pass bf16 split; acc 4 n8-tiles
__device__ __forceinline__ void mma_chunk(float acc[][4], int accBase,
                                          uint32_t aHiB, uint32_t aLoB,
                                          uint32_t bHiB, uint32_t bLoB) {
#pragma unroll
    for (int ks = 0; ks < 8; ks++) {
        uint32_t ko = ks * 32;
        uint32_t ah[4], al[4];
        ldm4(ah, aHiB + ko);
        ldm4(al, aLoB + ko);
#pragma unroll
        for (int p = 0; p < 2; p++) {
            uint32_t bh[4], blx[4];
            uint32_t po = (uint32_t)(p * 16 * A_STRIDE) + ko;
            ldm4(bh,  bHiB + po);
            ldm4(blx, bLoB + po);
            float* d0 = acc[accBase + p * 2];
            float* d1 = acc[accBase + p * 2 + 1];
            mma_bf16(d0, ah, bh[0],  bh[1]);
            mma_bf16(d0, ah, blx[0], blx[1]);
            mma_bf16(d0, al, bh[0],  bh[1]);
            mma_bf16(d1, ah, bh[2],  bh[3]);
            mma_bf16(d1, ah, blx[2], blx[3]);
            mma_bf16(d1, al, bh[2],  bh[3]);
        }
    }
}

__global__ __launch_bounds__(256, 2) void gemm_kernel(
    const float* __restrict__ agg, const float* __restrict__ h,
    const uint16_t* __restrict__ WlHi, const uint16_t* __restrict__ WlLo,
    const uint16_t* __restrict__ WrHi, const uint16_t* __restrict__ WrLo,
    const float* __restrict__ bias, float* __restrict__ C, int M)
{
    extern __shared__ char smem[];
    uint32_t su = smem_u32(smem);
    int tid = threadIdx.x;
    int lane = tid & 31;
    int wid = tid >> 5;
    int wm = wid & 3;        // 4 M-groups x 16 rows
    int wn = wid >> 2;       // 2 N-groups x 32 cols (within a 64-col chunk)
    int rowBase = blockIdx.x * 64;

    int lr = lane & 7, g = lane >> 3;
    uint32_t aOff = (uint32_t)((wm * 16 + lr + (g & 1) * 8) * A_STRIDE + (g >> 1) * 16);
    uint32_t bOff = (uint32_t)((wn * 32 + lr + (g >> 1) * 8) * A_STRIDE + (g & 1) * 16);
    uint32_t aHiB = su + SA_HI + aOff;
    uint32_t aLoB = su + SA_LO + aOff;
    uint32_t w0Hi = su + SW_BASE + bOff,          w0Lo = w0Hi + 17408;
    uint32_t w1Hi = su + SW_BASE + SW_BUF + bOff, w1Lo = w1Hi + 17408;

    float acc[8][4];
#pragma unroll
    for (int i = 0; i < 8; i++)
#pragma unroll
        for (int q = 0; q < 4; q++) acc[i][q] = 0.f;

    // prefetch both Wl chunks while converting A_agg
    stage_w_async(su, WlHi, WlLo, 0,  0, tid);
    stage_w_async(su, WlHi, WlLo, 64, 1, tid);
    stage_A(smem, agg, rowBase, M, tid);
    asm volatile("cp.async.wait_group 0;" ::: "memory");
    __syncthreads();                                   // (1)

    mma_chunk(acc, 0, aHiB, aLoB, w0Hi, w0Lo);         // cols 0-63 (Wl)
    __syncthreads();                                   // (2) buf0 free
    stage_w_async(su, WrHi, WrLo, 0, 0, tid);          // Wr chunk0 behind mma
    mma_chunk(acc, 4, aHiB, aLoB, w1Hi, w1Lo);         // cols 64-127 (Wl)
    __syncthreads();                                   // (3) buf1 + A free
    stage_w_async(su, WrHi, WrLo, 64, 1, tid);         // Wr chunk1 behind A staging
    stage_A(smem, h, rowBase, M, tid);
    asm volatile("cp.async.wait_group 0;" ::: "memory");
    __syncthreads();                                   // (4)

    mma_chunk(acc, 0, aHiB, aLoB, w0Hi, w0Lo);         // cols 0-63 (Wr)
    mma_chunk(acc, 4, aHiB, aLoB, w1Hi, w1Lo);         // cols 64-127 (Wr)

    // epilogue: bias + leaky, fp32 stores
    int r0 = rowBase + wm * 16 + (lane >> 2);
#pragma unroll
    for (int c = 0; c < 2; c++) {
#pragma unroll
        for (int p = 0; p < 2; p++) {
#pragma unroll
            for (int t = 0; t < 2; t++) {
                float* A = acc[c * 4 + p * 2 + t];
                int col = c * 64 + wn * 32 + p * 16 + t * 8 + 2 * (lane & 3);
                float b0 = bias[col], b1 = bias[col + 1];
                float v0 = A[0] + b0;
                float v1 = A[1] + b1;
                float v2 = A[2] + b0;
                float v3 = A[3] + b1;
                v0 = (v0 >= 0.f) ? v0 : SLOPE * v0;
                v1 = (v1 >= 0.f) ? v1 : SLOPE * v1;
                v2 = (v2 >= 0.f) ? v2 : SLOPE * v2;
                v3 = (v3 >= 0.f) ? v3 : SLOPE * v3;
                if (r0 < M)     *((float2*)&C[(size_t)r0 * NF + col])       = make_float2(v0, v1);
                if (r0 + 8 < M) *((float2*)&C[(size_t)(r0 + 8) * NF + col]) = make_float2(v2, v3);
            }
        }
    }
}

// ---------------- fused final layer: gather max + 3-dim output ----------------
__global__ __launch_bounds__(256) void aggout_kernel(
    const float* __restrict__ h,
    const float* __restrict__ Wl, const float* __restrict__ bl,
    const float* __restrict__ Wr, float* __restrict__ out)
{
    int warp = (blockIdx.x * blockDim.x + threadIdx.x) >> 5;
    int lane = threadIdx.x & 31;
    if (warp >= NN) return;
    const float4* h4 = (const float4*)h;
    int beg = g_rowptr[warp];
    int end = g_rowptr[warp + 1];
    float4 m = make_float4(-FLT_MAX, -FLT_MAX, -FLT_MAX, -FLT_MAX);
    int e = beg;
    for (; e + 8 <= end; e += 8) {
        float4 v0 = h4[g_col[e]     * 32 + lane];
        float4 v1 = h4[g_col[e + 1] * 32 + lane];
        float4 v2 = h4[g_col[e + 2] * 32 + lane];
        float4 v3 = h4[g_col[e + 3] * 32 + lane];
        float4 v4 = h4[g_col[e + 4] * 32 + lane];
        float4 v5 = h4[g_col[e + 5] * 32 + lane];
        float4 v6 = h4[g_col[e + 6] * 32 + lane];
        float4 v7 = h4[g_col[e + 7] * 32 + lane];
        m = fmax4(m, fmax4(fmax4(fmax4(v0, v1), fmax4(v2, v3)),
                           fmax4(fmax4(v4, v5), fmax4(v6, v7))));
    }
    for (; e < end; e++) m = fmax4(m, h4[g_col[e] * 32 + lane]);
    if (beg == end) m = make_float4(0.f, 0.f, 0.f, 0.f);

    float4 hv = h4[warp * 32 + lane];
#pragma unroll
    for (int o = 0; o < 3; o++) {
        float4 wl = ((const float4*)Wl)[o * 32 + lane];
        float4 wr = ((const float4*)Wr)[o * 32 + lane];
        float s = m.x * wl.x + m.y * wl.y + m.z * wl.z + m.w * wl.w
                + hv.x * wr.x + hv.y * wr.y + hv.z * wr.z + hv.w * wr.w;
#pragma unroll
        for (int off = 16; off; off >>= 1)
            s += __shfl_xor_sync(0xffffffff, s, off);
        if (lane == 0) out[warp * 3 + o] = tanhf(s + bl[o]) * 0.5f;
    }
}

// ---------------- host launcher ----------------
extern "C" void kernel_launch(void* const* d_in, const int* in_sizes, int n_in,
                              void* d_out, int out_size)
{
    const float* x      = (const float*)d_in[0];
    const int*   ei     = (const int*)d_in[1];
    const float* Wl     = (const float*)d_in[2];
    const float* bl     = (const float*)d_in[3];
    const float* Wr     = (const float*)d_in[4];
    const float* Wl_out = (const float*)d_in[5];
    const float* bl_out = (const float*)d_in[6];
    const float* Wr_out = (const float*)d_in[7];
    float* out = (float*)d_out;

    const int* src = ei;
    const int* dst = ei + NE;

    void *pH0, *pH1, *pAgg, *pWlHi, *pWlLo, *pWrHi, *pWrLo;
    cudaGetSymbolAddress(&pH0, g_h0);
    cudaGetSymbolAddress(&pH1, g_h1);
    cudaGetSymbolAddress(&pAgg, g_agg);
    cudaGetSymbolAddress(&pWlHi, g_WlHi);
    cudaGetSymbolAddress(&pWlLo, g_WlLo);
    cudaGetSymbolAddress(&pWrHi, g_WrHi);
    cudaGetSymbolAddress(&pWrLo, g_WrLo);
    float* h0  = (float*)pH0;
    float* h1  = (float*)pH1;
    float* agg = (float*)pAgg;
    uint16_t* wlHi = (uint16_t*)pWlHi;
    uint16_t* wlLo = (uint16_t*)pWlLo;
    uint16_t* wrHi = (uint16_t*)pWrHi;
    uint16_t* wrLo = (uint16_t*)pWrLo;

    cudaFuncSetAttribute(gemm_kernel, cudaFuncAttributeMaxDynamicSharedMemorySize, SM_TOT);

    // CSR build (3 launches)
    hist_kernel<<<(NE + 255) / 256, 256>>>(dst, Wl, Wr);
    scan_kernel<<<1, 1024>>>();
    fill_kernel<<<(NE + 255) / 256, 256>>>(src, dst);

    const int AGG_BLOCKS  = (NN + 7) / 8;
    const int GEMM_BLOCKS = (NN + 63) / 64;

    const float* cur = x;
    for (int i = 0; i < NL; i++) {
        agg_kernel<<<AGG_BLOCKS, 256>>>(cur, agg);
        float* nxt = (i & 1) ? h1 : h0;
        gemm_kernel<<<GEMM_BLOCKS, 256, SM_TOT>>>(
            agg, cur,
            wlHi + (size_t)i * NF * NF, wlLo + (size_t)i * NF * NF,
            wrHi + (size_t)i * NF * NF, wrLo + (size_t)i * NF * NF,
            bl + i * NF, nxt, NN);
        cur = nxt;
    }

    // fused final aggregation + output conv
    aggout_kernel<<<AGG_BLOCKS, 256>>>(cur, Wl_out, bl_out, Wr_out, out);
}